// round 7
// baseline (speedup 1.0000x reference)
#include <cuda_runtime.h>
#include <cuda_bf16.h>
#include <cstdint>

// Chunked-parallel scan of:  s = sigmoid(10*(s + (Wx+b)_t - 0.5)),  pred_t = x_t . s
// Run in t = 2s-1 domain:  t' = tanh(2.5 t + 5(Wx+b)),
// pred = 0.5*(x.t) + 0.5*(x0+x1+x2).  One MUFU.TANH per component per step.
//
// R7: 2 independent chunks per thread (6 tanh chains) to hide the serial
// FFMA->MUFU step latency that bound R6 (issue was 32% with nothing saturated).
// Warp owns 64 consecutive chunks; lane l runs chunks l and l+32 interleaved.
// Private per-warp double-buffered smem tiles, __syncwarp only.

static constexpr int CHUNK  = 32;                 // steps per chunk
static constexpr int WM     = 16;                 // warmup steps
static constexpr int TS     = 8;                  // steps per tile
static constexpr int TPB    = 128;                // 4 warps
static constexpr int WPB    = TPB / 32;
static constexpr int CPT    = 2;                  // chunks per thread
static constexpr int ROWS_W = 32 * CPT;           // 64 chunk-rows per warp
static constexpr int WTILES = WM / TS;            // 2
static constexpr int NTILES = (WM + CHUNK) / TS;  // 6
static constexpr int ROWF4  = TS * 3 / 4;         // 6 float4 per row per tile
static constexpr int PITCH  = 7;                  // conflict-free row pitch (float4)
static constexpr int XBUF_W = ROWS_W * PITCH;     // 448 f4 per buffer per warp
static constexpr int SMEM_BYTES = WPB * 2 * XBUF_W * 16;  // 57344 B

__device__ __forceinline__ float tanhapx(float z) {
    float r; asm("tanh.approx.f32 %0, %1;" : "=f"(r) : "f"(z)); return r;
}
__device__ __forceinline__ void cp16(unsigned int dst, const void* src) {
    asm volatile("cp.async.cg.shared.global [%0], [%1], 16;" :: "r"(dst), "l"(src));
}

__global__ void __launch_bounds__(TPB, 4)
updater_kernel(const float* __restrict__ x,
               const float* __restrict__ Wg,
               const float* __restrict__ bg,
               const float* __restrict__ net0,
               float* __restrict__ out)
{
    extern __shared__ float4 sm[];

    const int lane    = threadIdx.x & 31;
    const int wid     = threadIdx.x >> 5;
    const int chunk0w = blockIdx.x * (TPB * CPT) + wid * ROWS_W;
    const bool first  = (blockIdx.x == 0) && (wid == 0) && (lane == 0);

    // u5 = 5*(W x + b)
    const float W00 = 5.f*Wg[0], W01 = 5.f*Wg[1], W02 = 5.f*Wg[2];
    const float W10 = 5.f*Wg[3], W11 = 5.f*Wg[4], W12 = 5.f*Wg[5];
    const float W20 = 5.f*Wg[6], W21 = 5.f*Wg[7], W22 = 5.f*Wg[8];
    const float c0 = 5.f*bg[0], c1 = 5.f*bg[1], c2 = 5.f*bg[2];

    const float4* __restrict__ xf4 = reinterpret_cast<const float4*>(x);
    float4* __restrict__ of4 = reinterpret_cast<float4*>(out);

    float4* xw = sm + wid * (2 * XBUF_W);               // this warp's slice
    const unsigned int sbase = (unsigned int)__cvta_generic_to_shared(xw);

    // Cooperative per-warp tile load: 64 rows x 6 f4 each tile.
    auto issue = [&](int jt) {
        unsigned int bofs = sbase + (unsigned int)((jt & 1) * XBUF_W) * 16u;
        #pragma unroll
        for (int l = 0; l < ROWS_W * ROWF4 / 32; ++l) {   // 12 per lane
            int f   = lane + 32 * l;            // 0..383, bijective over (seg,off)
            int seg = f / ROWF4;
            int off = f - seg * ROWF4;
            int g   = (chunk0w + seg) * (CHUNK * 3 / 4) + (jt - WTILES) * ROWF4 + off;
            if (g < 0) g = 0;                   // only global chunk 0's discarded warmup
            cp16(bofs + (unsigned int)(seg * PITCH + off) * 16u, xf4 + g);
        }
        asm volatile("cp.async.commit_group;");
    };

    issue(0);

    // Two independent states (t-domain), midpoint seed s=0.5 -> t=0.
    float a0 = 0.f, a1 = 0.f, a2 = 0.f;   // chunk A = chunk0w + lane
    float b0 = 0.f, b1 = 0.f, b2 = 0.f;   // chunk B = chunk0w + lane + 32

    #pragma unroll 1
    for (int j = 0; j < NTILES; ++j) {
        if (j + 1 < NTILES) { issue(j + 1); asm volatile("cp.async.wait_group 1;"); }
        else                {               asm volatile("cp.async.wait_group 0;"); }
        __syncwarp();

        const float4* myA = xw + (j & 1) * XBUF_W + lane * PITCH;
        const float4* myB = myA + 32 * PITCH;

        if (j < WTILES) {
            // ---- warmup: both chunks, interleaved ----
            #pragma unroll
            for (int g = 0; g < TS / 4; ++g) {
                float4 pA = myA[3*g], qA = myA[3*g+1], rA = myA[3*g+2];
                float4 pB = myB[3*g], qB = myB[3*g+1], rB = myB[3*g+2];
                auto wstep2 = [&](float A0, float A1, float A2,
                                  float B0, float B1, float B2) {
                    float uA0 = fmaf(W00, A0, fmaf(W01, A1, fmaf(W02, A2, c0)));
                    float uB0 = fmaf(W00, B0, fmaf(W01, B1, fmaf(W02, B2, c0)));
                    float uA1 = fmaf(W10, A0, fmaf(W11, A1, fmaf(W12, A2, c1)));
                    float uB1 = fmaf(W10, B0, fmaf(W11, B1, fmaf(W12, B2, c1)));
                    float uA2 = fmaf(W20, A0, fmaf(W21, A1, fmaf(W22, A2, c2)));
                    float uB2 = fmaf(W20, B0, fmaf(W21, B1, fmaf(W22, B2, c2)));
                    a0 = tanhapx(fmaf(2.5f, a0, uA0));
                    b0 = tanhapx(fmaf(2.5f, b0, uB0));
                    a1 = tanhapx(fmaf(2.5f, a1, uA1));
                    b1 = tanhapx(fmaf(2.5f, b1, uB1));
                    a2 = tanhapx(fmaf(2.5f, a2, uA2));
                    b2 = tanhapx(fmaf(2.5f, b2, uB2));
                };
                wstep2(pA.x, pA.y, pA.z,  pB.x, pB.y, pB.z);
                wstep2(pA.w, qA.x, qA.y,  pB.w, qB.x, qB.y);
                wstep2(qA.z, qA.w, rA.x,  qB.z, qB.w, rB.x);
                wstep2(rA.y, rA.z, rA.w,  rB.y, rB.z, rB.w);
            }
        } else {
            if (j == WTILES && first) {
                a0 = fmaf(2.f, net0[0], -1.f);
                a1 = fmaf(2.f, net0[1], -1.f);
                a2 = fmaf(2.f, net0[2], -1.f);
            }
            int jm = j - WTILES;
            float4* odA = of4 + (long)(chunk0w + lane) * (CHUNK / 4) + jm * 2;
            float4* odB = odA + 32 * (CHUNK / 4);
            #pragma unroll
            for (int g = 0; g < TS / 4; ++g) {
                float4 pA = myA[3*g], qA = myA[3*g+1], rA = myA[3*g+2];
                float4 pB = myB[3*g], qB = myB[3*g+1], rB = myB[3*g+2];
                float resA[4], resB[4];
                auto mstep2 = [&](int i, float A0, float A1, float A2,
                                         float B0, float B1, float B2) {
                    float uA0 = fmaf(W00, A0, fmaf(W01, A1, fmaf(W02, A2, c0)));
                    float uB0 = fmaf(W00, B0, fmaf(W01, B1, fmaf(W02, B2, c0)));
                    float uA1 = fmaf(W10, A0, fmaf(W11, A1, fmaf(W12, A2, c1)));
                    float uB1 = fmaf(W10, B0, fmaf(W11, B1, fmaf(W12, B2, c1)));
                    float uA2 = fmaf(W20, A0, fmaf(W21, A1, fmaf(W22, A2, c2)));
                    float uB2 = fmaf(W20, B0, fmaf(W21, B1, fmaf(W22, B2, c2)));
                    a0 = tanhapx(fmaf(2.5f, a0, uA0));
                    b0 = tanhapx(fmaf(2.5f, b0, uB0));
                    a1 = tanhapx(fmaf(2.5f, a1, uA1));
                    b1 = tanhapx(fmaf(2.5f, b1, uB1));
                    a2 = tanhapx(fmaf(2.5f, a2, uA2));
                    b2 = tanhapx(fmaf(2.5f, b2, uB2));
                    float hA = fmaf(0.5f, A2, fmaf(0.5f, A1, 0.5f * A0));
                    float hB = fmaf(0.5f, B2, fmaf(0.5f, B1, 0.5f * B0));
                    float dA = fmaf(A0, a0, fmaf(A1, a1, A2 * a2));
                    float dB = fmaf(B0, b0, fmaf(B1, b1, B2 * b2));
                    resA[i] = fmaf(0.5f, dA, hA);
                    resB[i] = fmaf(0.5f, dB, hB);
                };
                mstep2(0, pA.x, pA.y, pA.z,  pB.x, pB.y, pB.z);
                mstep2(1, pA.w, qA.x, qA.y,  pB.w, qB.x, qB.y);
                mstep2(2, qA.z, qA.w, rA.x,  qB.z, qB.w, rB.x);
                mstep2(3, rA.y, rA.z, rA.w,  rB.y, rB.z, rB.w);
                odA[g] = make_float4(resA[0], resA[1], resA[2], resA[3]);
                odB[g] = make_float4(resB[0], resB[1], resB[2], resB[3]);
            }
        }
        __syncwarp();      // tile j consumed: buffer (j&1) free for tile j+2
    }
}

extern "C" void kernel_launch(void* const* d_in, const int* in_sizes, int n_in,
                              void* d_out, int out_size)
{
    const float* x    = (const float*)d_in[0];
    const float* W    = (const float*)d_in[1];
    const float* b    = (const float*)d_in[2];
    const float* net0 = (const float*)d_in[3];
    float* out = (float*)d_out;

    cudaFuncSetAttribute(updater_kernel,
                         cudaFuncAttributeMaxDynamicSharedMemorySize, SMEM_BYTES);

    int n       = in_sizes[0] / 3;          // B = 4194304
    int nchunks = n / CHUNK;                // 131072
    int blocks  = nchunks / (TPB * CPT);    // 512
    updater_kernel<<<blocks, TPB, SMEM_BYTES>>>(x, W, b, net0, out);
}

// round 8
// speedup vs baseline: 1.9734x; 1.9734x over previous
#include <cuda_runtime.h>
#include <cuda_bf16.h>
#include <cstdint>

// Chunked-parallel scan of:  s = sigmoid(10*(s + (Wx+b)_t - 0.5)),  pred_t = x_t . s
// Run in t = 2s-1 domain:  t' = tanh(2.5 t + 5(Wx+b)),
// pred = 0.5*(x.t) + 0.5*(x0+x1+x2).  One MUFU.TANH per component per step.
//
// R8: one-shot deep prefetch. Each warp cp.asyncs its FULL 48-step window
// (36 f4/lane) in 3 commit groups, then drains progressively (warmup computes
// under the main data's latency). No tile loop, no block barriers. Preds are
// staged into the consumed warmup smem slots and stored fully coalesced.

static constexpr int CHUNK  = 32;               // steps per thread
static constexpr int WM     = 16;               // warmup steps
static constexpr int TPB    = 128;              // 4 warps
static constexpr int WPB    = TPB / 32;
static constexpr int ROWF4  = (WM + CHUNK) * 3 / 4;   // 36 f4 per lane window
static constexpr int SECF4  = 12;               // f4 per commit-group section
static constexpr int PITCH  = 37;               // row pitch (f4), odd -> conflict-free
static constexpr int WSLICE = 32 * PITCH;       // 1184 f4 per warp
static constexpr int SMEM_BYTES = WPB * WSLICE * 16;   // 75776 B

__device__ __forceinline__ float tanhapx(float z) {
    float r; asm("tanh.approx.f32 %0, %1;" : "=f"(r) : "f"(z)); return r;
}
__device__ __forceinline__ void cp16(unsigned int dst, const void* src) {
    asm volatile("cp.async.cg.shared.global [%0], [%1], 16;" :: "r"(dst), "l"(src));
}

__global__ void __launch_bounds__(TPB, 2)
updater_kernel(const float* __restrict__ x,
               const float* __restrict__ Wg,
               const float* __restrict__ bg,
               const float* __restrict__ net0,
               float* __restrict__ out)
{
    extern __shared__ float4 sm[];

    const int lane    = threadIdx.x & 31;
    const int wid     = threadIdx.x >> 5;
    const int chunk0w = blockIdx.x * TPB + wid * 32;
    const bool first  = (blockIdx.x == 0) && (wid == 0) && (lane == 0);

    // u5 = 5*(W x + b)
    const float W00 = 5.f*Wg[0], W01 = 5.f*Wg[1], W02 = 5.f*Wg[2];
    const float W10 = 5.f*Wg[3], W11 = 5.f*Wg[4], W12 = 5.f*Wg[5];
    const float W20 = 5.f*Wg[6], W21 = 5.f*Wg[7], W22 = 5.f*Wg[8];
    const float c0 = 5.f*bg[0], c1 = 5.f*bg[1], c2 = 5.f*bg[2];

    const float4* __restrict__ xf4 = reinterpret_cast<const float4*>(x);
    float4* __restrict__ of4 = reinterpret_cast<float4*>(out);

    float4* xw = sm + wid * WSLICE;    // this warp's 32 rows, pitch 37
    const unsigned int sbase = (unsigned int)__cvta_generic_to_shared(xw);

    // ---- one-shot prefetch: 3 sections x 12 f4/row, cooperative & coalesced ----
    // Row r covers global f4 [ (chunk0w+r)*24 - 12 , +36 ): 16 warmup + 32 main steps.
    #pragma unroll
    for (int s = 0; s < 3; ++s) {
        #pragma unroll
        for (int l = 0; l < SECF4; ++l) {
            int f   = lane + 32 * l;             // 0..383
            int seg = f / SECF4;
            int off = s * SECF4 + f - seg * SECF4;
            long g  = (long)(chunk0w + seg) * 24 - 12 + off;
            if (g < 0) g = 0;                    // only chunk 0's discarded warmup
            cp16(sbase + (unsigned int)(seg * PITCH + off) * 16u, xf4 + g);
        }
        asm volatile("cp.async.commit_group;");
    }

    float t0 = 0.f, t1 = 0.f, t2 = 0.f;          // midpoint seed (s = 0.5)
    float4* my = xw + lane * PITCH;

    // ---- warmup: section 0 (f4 0..11) ----
    asm volatile("cp.async.wait_group 2;");
    __syncwarp();
    #pragma unroll
    for (int g = 0; g < WM / 4; ++g) {
        float4 p = my[3*g], q = my[3*g+1], r = my[3*g+2];
        auto wstep = [&](float X0, float X1, float X2) {
            float u0 = fmaf(W00, X0, fmaf(W01, X1, fmaf(W02, X2, c0)));
            float u1 = fmaf(W10, X0, fmaf(W11, X1, fmaf(W12, X2, c1)));
            float u2 = fmaf(W20, X0, fmaf(W21, X1, fmaf(W22, X2, c2)));
            t0 = tanhapx(fmaf(2.5f, t0, u0));
            t1 = tanhapx(fmaf(2.5f, t1, u1));
            t2 = tanhapx(fmaf(2.5f, t2, u2));
        };
        wstep(p.x, p.y, p.z);
        wstep(p.w, q.x, q.y);
        wstep(q.z, q.w, r.x);
        wstep(r.y, r.z, r.w);
    }
    if (first) {
        t0 = fmaf(2.f, net0[0], -1.f);
        t1 = fmaf(2.f, net0[1], -1.f);
        t2 = fmaf(2.f, net0[2], -1.f);
    }

    // ---- main pass: two halves, draining sections 1 then 2 ----
    auto mstep = [&](float X0, float X1, float X2) -> float {
        float u0 = fmaf(W00, X0, fmaf(W01, X1, fmaf(W02, X2, c0)));
        float u1 = fmaf(W10, X0, fmaf(W11, X1, fmaf(W12, X2, c1)));
        float u2 = fmaf(W20, X0, fmaf(W21, X1, fmaf(W22, X2, c2)));
        t0 = tanhapx(fmaf(2.5f, t0, u0));
        t1 = tanhapx(fmaf(2.5f, t1, u1));
        t2 = tanhapx(fmaf(2.5f, t2, u2));
        float h = fmaf(0.5f, X2, fmaf(0.5f, X1, 0.5f * X0));
        float d = fmaf(X0, t0, fmaf(X1, t1, X2 * t2));
        return fmaf(0.5f, d, h);
    };

    #pragma unroll
    for (int half = 0; half < 2; ++half) {
        if (half == 0) { asm volatile("cp.async.wait_group 1;"); }
        else           { asm volatile("cp.async.wait_group 0;"); }
        __syncwarp();
        #pragma unroll
        for (int g = 0; g < 4; ++g) {
            int gg = half * 4 + g;               // 0..7
            float4 p = my[SECF4 + 3*gg], q = my[SECF4 + 3*gg + 1], r = my[SECF4 + 3*gg + 2];
            float4 res;
            res.x = mstep(p.x, p.y, p.z);
            res.y = mstep(p.w, q.x, q.y);
            res.z = mstep(q.z, q.w, r.x);
            res.w = mstep(r.y, r.z, r.w);
            my[gg] = res;                        // stash pred in consumed warmup slot
        }
    }
    __syncwarp();

    // ---- coalesced store: 32 rows x 8 pred f4 -> 4KB contiguous per warp ----
    #pragma unroll
    for (int l = 0; l < 8; ++l) {
        int f   = lane + 32 * l;                 // 0..255
        int seg = f >> 3;
        int off = f & 7;
        of4[(long)(chunk0w + seg) * 8 + off] = xw[seg * PITCH + off];
    }
}

extern "C" void kernel_launch(void* const* d_in, const int* in_sizes, int n_in,
                              void* d_out, int out_size)
{
    const float* x    = (const float*)d_in[0];
    const float* W    = (const float*)d_in[1];
    const float* b    = (const float*)d_in[2];
    const float* net0 = (const float*)d_in[3];
    float* out = (float*)d_out;

    cudaFuncSetAttribute(updater_kernel,
                         cudaFuncAttributeMaxDynamicSharedMemorySize, SMEM_BYTES);

    int n       = in_sizes[0] / 3;     // B = 4194304
    int nchunks = n / CHUNK;           // 131072
    int blocks  = nchunks / TPB;       // 1024
    updater_kernel<<<blocks, TPB, SMEM_BYTES>>>(x, W, b, net0, out);
}

// round 11
// speedup vs baseline: 2.2366x; 1.1333x over previous
#include <cuda_runtime.h>
#include <cuda_bf16.h>
#include <cstdint>

// Chunked-parallel scan of:  s = sigmoid(10*(s + (Wx+b)_t - 0.5)),  pred_t = x_t . s
// Run in t = 2s-1 domain:  t' = tanh(2.5 t + 5(Wx+b)),
// pred = 0.5*(x.t) + 0.5*(x0+x1+x2).  One MUFU.TANH per component per step.
//
// R11: shared flat warp window (R10 with the group split fixed). A warp's
// 48-step region (16 warmup + 32 main per lane; consecutive lanes overlap by
// 12 f4) is ONE contiguous 780-f4 global span, cp.async'd cooperatively in
// 2 commit groups: G0 = 33 half-spans of warmup-phase data (396 f4),
// G1 = 32 half-spans of main-phase data (384 f4). Padded layout
// slot = span*25 + w is conflict-free at lane stride 25. Preds stashed in
// consumed own-lane slots, stored fully coalesced. Warp-local sync only.

static constexpr int CHUNK  = 32;               // steps per thread (24 f4)
static constexpr int WM     = 16;               // warmup steps (12 f4)
static constexpr int TPB    = 128;              // 4 warps
static constexpr int WPB    = TPB / 32;
static constexpr int G0N    = 33 * 12;          // 396 f4 (w in [0,12), span 0..32)
static constexpr int G1N    = 32 * 12;          // 384 f4 (w in [12,24), span 0..31)
static constexpr int WSLICE = 812;              // max slot 32*25+11=811, +1
static constexpr int SMEM_BYTES = WPB * WSLICE * 16;   // 51968 B

__device__ __forceinline__ float tanhapx(float z) {
    float r; asm("tanh.approx.f32 %0, %1;" : "=f"(r) : "f"(z)); return r;
}
__device__ __forceinline__ void cp16(unsigned int dst, const void* src) {
    asm volatile("cp.async.cg.shared.global [%0], [%1], 16;" :: "r"(dst), "l"(src));
}

__global__ void __launch_bounds__(TPB, 4)
updater_kernel(const float* __restrict__ x,
               const float* __restrict__ Wg,
               const float* __restrict__ bg,
               const float* __restrict__ net0,
               float* __restrict__ out)
{
    extern __shared__ float4 sm[];

    const int lane = threadIdx.x & 31;
    const int wid  = threadIdx.x >> 5;
    const int w0c  = blockIdx.x * TPB + wid * 32;       // warp's first chunk
    const bool first = (blockIdx.x == 0) && (wid == 0) && (lane == 0);

    // u5 = 5*(W x + b)
    const float W00 = 5.f*Wg[0], W01 = 5.f*Wg[1], W02 = 5.f*Wg[2];
    const float W10 = 5.f*Wg[3], W11 = 5.f*Wg[4], W12 = 5.f*Wg[5];
    const float W20 = 5.f*Wg[6], W21 = 5.f*Wg[7], W22 = 5.f*Wg[8];
    const float c0 = 5.f*bg[0], c1 = 5.f*bg[1], c2 = 5.f*bg[2];

    const float4* __restrict__ xf4 = reinterpret_cast<const float4*>(x);
    float4* __restrict__ of4 = reinterpret_cast<float4*>(out);

    float4* xw = sm + wid * WSLICE;
    const unsigned int sbase = (unsigned int)__cvta_generic_to_shared(xw);
    const long gbase = (long)w0c * 24 - 12;             // window start (global f4)

    // ---- group 0: warmup-phase data, w in [0,12), spans 0..32 (396 f4) ----
    #pragma unroll
    for (int l = 0; l < 13; ++l) {
        int i = lane + 32 * l;                  // 0..415
        if (i < G0N) {
            int span = i / 12, w = i - span * 12;
            long g = gbase + span * 24 + w;
            if (g < 0) g = 0;                   // only global chunk 0's discarded warmup
            cp16(sbase + (unsigned int)(span * 25 + w) * 16u, xf4 + g);
        }
    }
    asm volatile("cp.async.commit_group;");

    // ---- group 1: main-phase data, w in [12,24), spans 0..31 (384 f4) ----
    #pragma unroll
    for (int l = 0; l < 12; ++l) {
        int i = lane + 32 * l;                  // 0..383, bijective
        int span = i / 12, w = i - span * 12;
        long g = gbase + span * 24 + 12 + w;    // >= 0 always (span*24+12 > 12)
        cp16(sbase + (unsigned int)(span * 25 + 12 + w) * 16u, xf4 + g);
    }
    asm volatile("cp.async.commit_group;");

    float t0 = 0.f, t1 = 0.f, t2 = 0.f;         // midpoint seed (s = 0.5)
    float4* my = xw + lane * 25;                // lane base; j<24: slot=j, j>=24: slot=j+1

    // ---- warmup: 16 steps, j = 0..11 (own G0 region) ----
    asm volatile("cp.async.wait_group 1;");
    __syncwarp();
    #pragma unroll
    for (int g = 0; g < WM / 4; ++g) {
        float4 p = my[3*g], q = my[3*g+1], r = my[3*g+2];
        auto wstep = [&](float X0, float X1, float X2) {
            float u0 = fmaf(W00, X0, fmaf(W01, X1, fmaf(W02, X2, c0)));
            float u1 = fmaf(W10, X0, fmaf(W11, X1, fmaf(W12, X2, c1)));
            float u2 = fmaf(W20, X0, fmaf(W21, X1, fmaf(W22, X2, c2)));
            t0 = tanhapx(fmaf(2.5f, t0, u0));
            t1 = tanhapx(fmaf(2.5f, t1, u1));
            t2 = tanhapx(fmaf(2.5f, t2, u2));
        };
        wstep(p.x, p.y, p.z);
        wstep(p.w, q.x, q.y);
        wstep(q.z, q.w, r.x);
        wstep(r.y, r.z, r.w);
    }
    if (first) {
        t0 = fmaf(2.f, net0[0], -1.f);
        t1 = fmaf(2.f, net0[1], -1.f);
        t2 = fmaf(2.f, net0[2], -1.f);
    }

    // ---- main: 32 steps, j = 12..35 (j>=24 -> lane+1's G0 slots, +1 bump) ----
    asm volatile("cp.async.wait_group 0;");
    __syncwarp();

    auto mstep = [&](float X0, float X1, float X2) -> float {
        float u0 = fmaf(W00, X0, fmaf(W01, X1, fmaf(W02, X2, c0)));
        float u1 = fmaf(W10, X0, fmaf(W11, X1, fmaf(W12, X2, c1)));
        float u2 = fmaf(W20, X0, fmaf(W21, X1, fmaf(W22, X2, c2)));
        t0 = tanhapx(fmaf(2.5f, t0, u0));
        t1 = tanhapx(fmaf(2.5f, t1, u1));
        t2 = tanhapx(fmaf(2.5f, t2, u2));
        float h = fmaf(0.5f, X2, fmaf(0.5f, X1, 0.5f * X0));
        float d = fmaf(X0, t0, fmaf(X1, t1, X2 * t2));
        return fmaf(0.5f, d, h);
    };

    #pragma unroll
    for (int g = 0; g < 8; ++g) {
        int j0 = 12 + 3*g, j1 = 13 + 3*g, j2 = 14 + 3*g;
        float4 p = my[j0 + (j0 >= 24 ? 1 : 0)];
        float4 q = my[j1 + (j1 >= 24 ? 1 : 0)];
        float4 r = my[j2 + (j2 >= 24 ? 1 : 0)];
        float4 res;
        res.x = mstep(p.x, p.y, p.z);
        res.y = mstep(p.w, q.x, q.y);
        res.z = mstep(q.z, q.w, r.x);
        res.w = mstep(r.y, r.z, r.w);
        my[12 + g] = res;      // own consumed G1 slot (write after its reads; no other reader)
    }
    __syncwarp();

    // ---- coalesced store: 32 chunks x 8 pred f4 = 512B per warp-instruction ----
    #pragma unroll
    for (int l = 0; l < 8; ++l) {
        int f   = lane + 32 * l;               // 0..255
        int seg = f >> 3;
        int off = f & 7;
        of4[(long)(w0c + seg) * 8 + off] = xw[seg * 25 + 12 + off];
    }
}

extern "C" void kernel_launch(void* const* d_in, const int* in_sizes, int n_in,
                              void* d_out, int out_size)
{
    const float* x    = (const float*)d_in[0];
    const float* W    = (const float*)d_in[1];
    const float* b    = (const float*)d_in[2];
    const float* net0 = (const float*)d_in[3];
    float* out = (float*)d_out;

    cudaFuncSetAttribute(updater_kernel,
                         cudaFuncAttributeMaxDynamicSharedMemorySize, SMEM_BYTES);

    int n       = in_sizes[0] / 3;     // B = 4194304
    int nchunks = n / CHUNK;           // 131072
    int blocks  = nchunks / TPB;       // 1024
    updater_kernel<<<blocks, TPB, SMEM_BYTES>>>(x, W, b, net0, out);
}